// round 4
// baseline (speedup 1.0000x reference)
#include <cuda_runtime.h>

// HMM forward, fused one-hot decode + scaled recurrence.
// B=512, T=4096, S=64, M=125.
// TWO warps per sequence: warp-half h owns output states 32h..32h+31.
// Split matvec: own-half (no cross-warp sync needed) BEFORE the CTA barrier,
// peer-half after -> barrier latency overlaps own-half compute.
// Renormalize every 8 steps, applied one step late (linear, exact).

#define BATCH 512
#define T_LEN 4096
#define S_DIM 64
#define M_DIM 125
#define ROW_BYTES (M_DIM * 4) /* 500 */
#define PAIRS 4               /* sequences per CTA */
#define THREADS (PAIRS * 64)  /* 256 */

typedef unsigned long long ull;

// ---------- f32x2 helpers ----------
__device__ __forceinline__ ull pk2(float x, float y) {
    ull r; asm("mov.b64 %0, {%1, %2};" : "=l"(r) : "f"(x), "f"(y)); return r;
}
__device__ __forceinline__ void upk2(ull v, float &x, float &y) {
    asm("mov.b64 {%0, %1}, %2;" : "=f"(x), "=f"(y) : "l"(v));
}
__device__ __forceinline__ void ffma2(ull &d, ull a, ull b) {
    asm("fma.rn.f32x2 %0, %1, %2, %0;" : "+l"(d) : "l"(a), "l"(b));
}
__device__ __forceinline__ ull fadd2(ull a, ull b) {
    ull r; asm("add.rn.f32x2 %0, %1, %2;" : "=l"(r) : "l"(a), "l"(b)); return r;
}

// ---------- one-hot decode ----------
__device__ __forceinline__ float wgt(int i) {
    return ((unsigned)i < (unsigned)M_DIM) ? (float)i : 0.0f;
}
__device__ __forceinline__ int compute_obs(float4 v, int s, int lane) {
    int b0 = 4 * lane - s;
    float p;
    p = v.x * wgt(b0);
    p = fmaf(v.y, wgt(b0 + 1), p);
    p = fmaf(v.z, wgt(b0 + 2), p);
    p = fmaf(v.w, wgt(b0 + 3), p);
    return __reduce_add_sync(0xffffffffu, (int)p);
}

// 16B-aligned 512B window covering row t (row stride 500B, seq base 16B-aligned).
__device__ __forceinline__ float4 ldx4(const char* xb, int t, int lane) {
    const float4* p = (const float4*)(xb + (((size_t)(unsigned)t * ROW_BYTES) & ~(size_t)15));
    return p[lane];  // cached: pair-mate warp hits L1
}

__global__ void __launch_bounds__(THREADS, 1)
hmm_forward_kernel(const float* __restrict__ x, const float* __restrict__ I,
                   const float* __restrict__ A, const float* __restrict__ Bm,
                   float* __restrict__ out) {
    __shared__ __align__(16) float sBm[M_DIM * S_DIM];       // 32000 B
    __shared__ __align__(16) float sAlpha[PAIRS][2][S_DIM];  // 2048 B
    __shared__ float sZ[PAIRS][2];                           // boundary partials

    const int lane = threadIdx.x & 31;
    const int w    = threadIdx.x >> 5;
    const int pair = w >> 1;
    const int half = w & 1;
    const int seq  = blockIdx.x * PAIRS + pair;
    const int j    = half * 32 + lane;   // output state owned by this lane
    const int oth  = half ^ 1;

    // cooperative Bm -> SMEM
    {
        const float4* src = (const float4*)Bm;
        float4* dst = (float4*)sBm;
        for (int i = threadIdx.x; i < (M_DIM * S_DIM) / 4; i += blockDim.x)
            dst[i] = src[i];
    }

    // A column j over k-pairs: Ac[p] = (A[2p][j], A[2p+1][j]), p=0..31.
    // Own half uses p in [16*half, 16*half+16), peer half the other 16.
    ull Ac[32];
#pragma unroll
    for (int p = 0; p < 32; p++)
        Ac[p] = pk2(A[(2 * p) * S_DIM + j], A[(2 * p + 1) * S_DIM + j]);
    const float Ij = I[j];

    __syncthreads();  // sBm ready

    const char* xb = (const char*)x + (size_t)seq * T_LEN * ROW_BYTES;

    // prime 8-deep x ring
    float4 xv[8];
#pragma unroll
    for (int r = 0; r < 8; r++) xv[r] = ldx4(xb, r, lane);

    int obs0 = compute_obs(xv[0], 0, lane);
    float e = sBm[obs0 * S_DIM + j];

    float ll  = 0.0f;  // accumulated in half==0
    float inv = 1.0f;  // deferred 1/Z, applied at K==0

    // ---- t = 0 : u = I ∘ E0 (raw) into buffer 0 ----
    {
        xv[0] = ldx4(xb, 8, lane);
        int obsn = compute_obs(xv[1], 1, lane);
        float en = sBm[obsn * S_DIM + j];
        sAlpha[pair][0][j] = Ij * e;
        __syncwarp();
        e = en;
    }

    // Step t (K = t&7): reads buffer R=(K+1)&1, writes K&1.
    // Phase 1 (pre-barrier): prefetch, next-obs decode, OWN-half matvec
    //   (own u was stored by this warp; __syncwarp at tail makes it visible).
    // __syncthreads: peer's STS from the previous step is now visible.
    // Phase 2: peer-half matvec, combine, scale/boundary, STS, __syncwarp.
#define STEP(t_i, K)                                                           \
    do {                                                                       \
        const int tcur = (t_i);                                                \
        xv[(K) & 7] = ldx4(xb, min(tcur + 8, T_LEN - 1), lane);                \
        int obsn = 0;                                                          \
        if (tcur + 1 < T_LEN)                                                  \
            obsn = compute_obs(xv[((K) + 1) & 7], (tcur + 1) & 3, lane);       \
        float en = sBm[obsn * S_DIM + j];                                      \
        const ulonglong2* apO =                                                \
            (const ulonglong2*)&sAlpha[pair][((K) + 1) & 1][half * 32];        \
        ull a0 = 0ull, a1 = 0ull;                                              \
        _Pragma("unroll")                                                      \
        for (int q = 0; q < 8; q++) {                                          \
            ulonglong2 wv = apO[q];                                            \
            ffma2(a0, wv.x, Ac[16 * half + 2 * q]);                            \
            ffma2(a1, wv.y, Ac[16 * half + 2 * q + 1]);                        \
        }                                                                      \
        __syncthreads();                                                       \
        float invL = inv;                                                      \
        if ((K) == 0) {                                                        \
            float2 pz = *(const float2*)&sZ[pair][0];                          \
            float z = pz.x + pz.y;                                             \
            invL = __fdividef(1.0f, z);                                        \
            if (half == 0) ll += __logf(z);                                    \
            inv = invL;                                                        \
        }                                                                      \
        const ulonglong2* apP =                                                \
            (const ulonglong2*)&sAlpha[pair][((K) + 1) & 1][oth * 32];         \
        ull a2 = 0ull, a3 = 0ull;                                              \
        _Pragma("unroll")                                                      \
        for (int q = 0; q < 8; q++) {                                          \
            ulonglong2 wv = apP[q];                                            \
            ffma2(a2, wv.x, Ac[16 * oth + 2 * q]);                             \
            ffma2(a3, wv.y, Ac[16 * oth + 2 * q + 1]);                         \
        }                                                                      \
        ull s2 = fadd2(fadd2(a0, a2), fadd2(a1, a3));                          \
        float sx, sy;                                                          \
        upk2(s2, sx, sy);                                                      \
        float u = (sx + sy) * e;                                               \
        if ((K) == 0) u *= invL;                                               \
        if ((K) == 7) {                                                        \
            float zp = u;                                                      \
            zp += __shfl_xor_sync(0xffffffffu, zp, 1);                         \
            zp += __shfl_xor_sync(0xffffffffu, zp, 2);                         \
            zp += __shfl_xor_sync(0xffffffffu, zp, 4);                         \
            zp += __shfl_xor_sync(0xffffffffu, zp, 8);                         \
            zp += __shfl_xor_sync(0xffffffffu, zp, 16);                        \
            if (lane == 0) sZ[pair][half] = zp;                                \
        }                                                                      \
        sAlpha[pair][(K) & 1][j] = u;                                         \
        __syncwarp();                                                          \
        e = en;                                                                \
    } while (0)

    // first partial block t = 1..7
#pragma unroll
    for (int t = 1; t < 8; ++t) STEP(t, t);

    // full blocks; final step t=4095 is a boundary (partials stored)
    for (int t0 = 8; t0 < T_LEN; t0 += 8) {
#pragma unroll
        for (int k = 0; k < 8; ++k) STEP(t0 + k, k);
    }
#undef STEP

    __syncthreads();  // make final sZ (written at t=4095) visible
    {
        float2 pz = *(const float2*)&sZ[pair][0];
        float z = pz.x + pz.y;
        if (half == 0) {
            ll += __logf(z);
            if (lane == 0) out[seq] = ll;
        }
    }
}

extern "C" void kernel_launch(void* const* d_in, const int* in_sizes, int n_in,
                              void* d_out, int out_size) {
    const float *x = nullptr, *I = nullptr, *A = nullptr, *Bm = nullptr;
    for (int i = 0; i < n_in; ++i) {
        switch (in_sizes[i]) {
            case BATCH * T_LEN * M_DIM: x  = (const float*)d_in[i]; break;
            case S_DIM:                 I  = (const float*)d_in[i]; break;
            case S_DIM * S_DIM:         A  = (const float*)d_in[i]; break;
            case M_DIM * S_DIM:         Bm = (const float*)d_in[i]; break;
            default: break;
        }
    }
    float* out = (float*)d_out;
    (void)out_size;
    hmm_forward_kernel<<<BATCH / PAIRS, THREADS>>>(x, I, A, Bm, out);
}

// round 5
// speedup vs baseline: 1.4292x; 1.4292x over previous
#include <cuda_runtime.h>

// HMM forward, fused one-hot decode + scaled recurrence.
// B=512, T=4096, S=64, M=125.
// TWO warps per sequence; warp-half h owns output states 32h..32h+31.
// Producer/consumer named barriers (arrive after STS, sync before peer read);
// own-half matvec overlaps the barrier. Z at block boundaries computed from
// the operands already loaded for the K==0 matvec (no shuffle reduce);
// 1/Z applied one step later at K==1 (linear => exact).

#define BATCH 512
#define T_LEN 4096
#define S_DIM 64
#define M_DIM 125
#define ROW_BYTES (M_DIM * 4) /* 500 */
#define PAIRS 4               /* sequences per CTA */
#define THREADS (PAIRS * 64)  /* 256 */

typedef unsigned long long ull;

// ---------- f32x2 helpers ----------
__device__ __forceinline__ ull pk2(float x, float y) {
    ull r; asm("mov.b64 %0, {%1, %2};" : "=l"(r) : "f"(x), "f"(y)); return r;
}
__device__ __forceinline__ void upk2(ull v, float &x, float &y) {
    asm("mov.b64 {%0, %1}, %2;" : "=f"(x), "=f"(y) : "l"(v));
}
__device__ __forceinline__ void ffma2(ull &d, ull a, ull b) {
    asm("fma.rn.f32x2 %0, %1, %2, %0;" : "+l"(d) : "l"(a), "l"(b));
}
__device__ __forceinline__ ull fadd2(ull a, ull b) {
    ull r; asm("add.rn.f32x2 %0, %1, %2;" : "=l"(r) : "l"(a), "l"(b)); return r;
}

// ---------- one-hot decode ----------
__device__ __forceinline__ float wgt(int i) {
    return ((unsigned)i < (unsigned)M_DIM) ? (float)i : 0.0f;
}
__device__ __forceinline__ int compute_obs(float4 v, int s, int lane) {
    int b0 = 4 * lane - s;
    float p;
    p = v.x * wgt(b0);
    p = fmaf(v.y, wgt(b0 + 1), p);
    p = fmaf(v.z, wgt(b0 + 2), p);
    p = fmaf(v.w, wgt(b0 + 3), p);
    return __reduce_add_sync(0xffffffffu, (int)p);
}

// 16B-aligned 512B window covering row t (row stride 500B, seq base 16B-aligned).
__device__ __forceinline__ float4 ldx4(const char* xb, int t, int lane) {
    const float4* p = (const float4*)(xb + (((size_t)(unsigned)t * ROW_BYTES) & ~(size_t)15));
    return p[lane];  // cached: pair-mate warp hits L1
}

// named-barrier helpers (ids 1..8; __syncthreads uses id 0)
__device__ __forceinline__ void bar_arrive(int id) {
    asm volatile("bar.arrive %0, 64;" :: "r"(id) : "memory");
}
__device__ __forceinline__ void bar_wait(int id) {
    asm volatile("bar.sync %0, 64;" :: "r"(id) : "memory");
}

__global__ void __launch_bounds__(THREADS, 1)
hmm_forward_kernel(const float* __restrict__ x, const float* __restrict__ I,
                   const float* __restrict__ A, const float* __restrict__ Bm,
                   float* __restrict__ out) {
    __shared__ __align__(16) float sBm[M_DIM * S_DIM];       // 32000 B
    __shared__ __align__(16) float sAlpha[PAIRS][2][S_DIM];  // 2048 B

    const int lane = threadIdx.x & 31;
    const int w    = threadIdx.x >> 5;
    const int pair = w >> 1;
    const int half = w & 1;
    const int seq  = blockIdx.x * PAIRS + pair;
    const int j    = half * 32 + lane;   // output state owned by this lane
    const int oth  = half ^ 1;
    const int bOwn = 1 + pair * 2 + half;   // I arrive here after my STS
    const int bPeer= 1 + pair * 2 + oth;    // I wait here for peer's STS

    // cooperative Bm -> SMEM
    {
        const float4* src = (const float4*)Bm;
        float4* dst = (float4*)sBm;
        for (int i = threadIdx.x; i < (M_DIM * S_DIM) / 4; i += blockDim.x)
            dst[i] = src[i];
    }

    // A column j over k-pairs: Ac[p] = (A[2p][j], A[2p+1][j]), p=0..31.
    ull Ac[32];
#pragma unroll
    for (int p = 0; p < 32; p++)
        Ac[p] = pk2(A[(2 * p) * S_DIM + j], A[(2 * p + 1) * S_DIM + j]);
    const float Ij = I[j];

    __syncthreads();  // sBm ready (id-0 barrier, once)

    const char* xb = (const char*)x + (size_t)seq * T_LEN * ROW_BYTES;

    // prime 8-deep x ring
    float4 xv[8];
#pragma unroll
    for (int r = 0; r < 8; r++) xv[r] = ldx4(xb, r, lane);

    int obs0 = compute_obs(xv[0], 0, lane);
    float e = sBm[obs0 * S_DIM + j];

    float ll  = 0.0f;  // accumulated in half==0 lanes
    float inv = 1.0f;  // deferred 1/Z, applied at K==1

    // ---- t = 0 : u = I ∘ E0 (raw) into buffer 0 ----
    {
        xv[0] = ldx4(xb, 8, lane);
        int obsn = compute_obs(xv[1], 1, lane);
        float en = sBm[obsn * S_DIM + j];
        sAlpha[pair][0][j] = Ij * e;
        __syncwarp();
        bar_arrive(bOwn);
        e = en;
    }

    // Step t (K = t&7): reads buffer R=(K+1)&1, writes K&1.
    // Phase 1 (no peer dep): x prefetch, next-obs decode, OWN-half matvec
    //   (own-half of buffer R written by this warp; __syncwarp'd).
    // bar_wait(bPeer): peer's STS of step t-1 now visible.
    // Phase 2: peer-half matvec, combine, boundary Z (K==0, from loaded
    //   operands), scale (K==1), STS, __syncwarp, bar_arrive(bOwn).
#define STEP(t_i, K)                                                           \
    do {                                                                       \
        const int tcur = (t_i);                                                \
        xv[(K) & 7] = ldx4(xb, min(tcur + 8, T_LEN - 1), lane);                \
        int obsn = 0;                                                          \
        if (tcur + 1 < T_LEN)                                                  \
            obsn = compute_obs(xv[((K) + 1) & 7], (tcur + 1) & 3, lane);       \
        float en = sBm[obsn * S_DIM + j];                                      \
        const ulonglong2* apO =                                                \
            (const ulonglong2*)&sAlpha[pair][((K) + 1) & 1][half * 32];        \
        ull a0 = 0ull, a1 = 0ull, zacc = 0ull;                                 \
        _Pragma("unroll")                                                      \
        for (int q = 0; q < 8; q++) {                                          \
            ulonglong2 wv = apO[q];                                            \
            ffma2(a0, wv.x, Ac[16 * half + 2 * q]);                            \
            ffma2(a1, wv.y, Ac[16 * half + 2 * q + 1]);                        \
            if ((K) == 0) { zacc = fadd2(zacc, wv.x); zacc = fadd2(zacc, wv.y); } \
        }                                                                      \
        bar_wait(bPeer);                                                       \
        const ulonglong2* apP =                                                \
            (const ulonglong2*)&sAlpha[pair][((K) + 1) & 1][oth * 32];         \
        ull a2 = 0ull, a3 = 0ull;                                              \
        _Pragma("unroll")                                                      \
        for (int q = 0; q < 8; q++) {                                          \
            ulonglong2 wv = apP[q];                                            \
            ffma2(a2, wv.x, Ac[16 * oth + 2 * q]);                             \
            ffma2(a3, wv.y, Ac[16 * oth + 2 * q + 1]);                         \
            if ((K) == 0) { zacc = fadd2(zacc, wv.x); zacc = fadd2(zacc, wv.y); } \
        }                                                                      \
        if ((K) == 0) {                                                        \
            float zx, zy;                                                      \
            upk2(zacc, zx, zy);                                                \
            float z = zx + zy;                                                 \
            inv = __fdividef(1.0f, z);                                         \
            if (half == 0) ll += __logf(z);                                    \
        }                                                                      \
        ull s2 = fadd2(fadd2(a0, a2), fadd2(a1, a3));                          \
        float sx, sy;                                                          \
        upk2(s2, sx, sy);                                                      \
        float u = (sx + sy) * e;                                               \
        if ((K) == 1) u *= inv;                                                \
        sAlpha[pair][(K) & 1][j] = u;                                          \
        __syncwarp();                                                          \
        bar_arrive(bOwn);                                                      \
        e = en;                                                                \
    } while (0)

    // first partial block t = 1..7 (K==1 uses inv=1.0: harmless)
#pragma unroll
    for (int t = 1; t < 8; ++t) STEP(t, t);

    // full blocks; final step t=4095 writes raw boundary into buf[1]
    for (int t0 = 8; t0 < T_LEN; t0 += 8) {
#pragma unroll
        for (int k = 0; k < 8; ++k) STEP(t0 + k, k);
    }
#undef STEP

    // epilogue: consume final arrive, sum final raw buffer -> last log Z
    bar_wait(bPeer);
    if (half == 0) {
        const ulonglong2* ap = (const ulonglong2*)&sAlpha[pair][1][0];
        ull zacc = 0ull;
#pragma unroll
        for (int q = 0; q < 16; q++) {
            ulonglong2 wv = ap[q];
            zacc = fadd2(zacc, wv.x);
            zacc = fadd2(zacc, wv.y);
        }
        float zx, zy;
        upk2(zacc, zx, zy);
        ll += __logf(zx + zy);
        if (lane == 0) out[seq] = ll;
    }
}

extern "C" void kernel_launch(void* const* d_in, const int* in_sizes, int n_in,
                              void* d_out, int out_size) {
    const float *x = nullptr, *I = nullptr, *A = nullptr, *Bm = nullptr;
    for (int i = 0; i < n_in; ++i) {
        switch (in_sizes[i]) {
            case BATCH * T_LEN * M_DIM: x  = (const float*)d_in[i]; break;
            case S_DIM:                 I  = (const float*)d_in[i]; break;
            case S_DIM * S_DIM:         A  = (const float*)d_in[i]; break;
            case M_DIM * S_DIM:         Bm = (const float*)d_in[i]; break;
            default: break;
        }
    }
    float* out = (float*)d_out;
    (void)out_size;
    hmm_forward_kernel<<<BATCH / PAIRS, THREADS>>>(x, I, A, Bm, out);
}